// round 16
// baseline (speedup 1.0000x reference)
#include <cuda_runtime.h>
#include <cuda_fp16.h>
#include <math.h>
#include <stdint.h>

#define B_   16
#define E_   768
#define H_   12
#define HD_  64
#define N_   197
#define NP_  196
#define L_   12
#define FF_  3072
#define ROWS_ (B_*N_)          // 3152
#define SQRTE 27.712812921102035f
#define EE_   (E_*E_)
#define FFE_  (FF_*E_)
#define PLANE_ (ROWS_*E_)

// packed fp16 weight layout: [QKV(3*NQ)] [O(NQ)] [UG interleaved(2*NUP)] [DOWN(NUP)]
#define NQ_   (L_*EE_)
#define NUP_  (L_*FFE_)
#define OFF_QKV  0
#define OFF_O    (3*NQ_)
#define OFF_UG   (4*NQ_)
#define OFF_DOWN (4*NQ_ + 2*NUP_)
#define WTOT_    (4*NQ_ + 3*NUP_)

// ---------------- scratch (device globals; no allocation allowed) ----------
__device__ float g_h[ROWS_*E_];
__device__ float g_t[4*PLANE_];
__device__ __half g_qkvh[ROWS_*3*E_];
__device__ __half g_act[ROWS_*E_];
__device__ __half g_act2[ROWS_*FF_];
__device__ __half g_w[WTOT_];

// ======================= mma.sync GEMM (unchanged from best) ================
#define BM 128
#define BN 128
#define BK 32
#define PADE 40
#define ARR_BYTES (128*PADE*2)
#define STAGE_BYTES (2*ARR_BYTES)
#define NSTAGE 4
#define GSMEM (NSTAGE*STAGE_BYTES)    // 81920

__device__ __forceinline__ uint32_t smem_u32(const void* p) {
    uint32_t a;
    asm("{ .reg .u64 t; cvta.to.shared.u64 t, %1; cvt.u32.u64 %0, t; }"
        : "=r"(a) : "l"(p));
    return a;
}
__device__ __forceinline__ void cp16(uint32_t dst, const void* src) {
    asm volatile("cp.async.cg.shared.global [%0], [%1], 16;"
                 :: "r"(dst), "l"(src) : "memory");
}
#define CP_COMMIT() asm volatile("cp.async.commit_group;" ::: "memory")
#define CP_WAIT2()  asm volatile("cp.async.wait_group 2;" ::: "memory")

#define LDSM4(r, addr) \
    asm volatile("ldmatrix.sync.aligned.m8n8.x4.shared.b16 {%0,%1,%2,%3}, [%4];" \
        : "=r"((r)[0]), "=r"((r)[1]), "=r"((r)[2]), "=r"((r)[3]) : "r"(addr))
#define MMA_F16(d, a, b0, b1) \
    asm volatile("mma.sync.aligned.m16n8k16.row.col.f32.f16.f16.f32 " \
        "{%0,%1,%2,%3}, {%4,%5,%6,%7}, {%8,%9}, {%0,%1,%2,%3};" \
        : "+f"((d)[0]), "+f"((d)[1]), "+f"((d)[2]), "+f"((d)[3]) \
        : "r"((a)[0]), "r"((a)[1]), "r"((a)[2]), "r"((a)[3]), \
          "r"(b0), "r"(b1))

__device__ __forceinline__ void load_stage(
        uint32_t sbase,
        const __half* __restrict__ A, const __half* __restrict__ W,
        int m0, int n0, int k0, int M, int lda, int tid) {
    #pragma unroll
    for (int i = 0; i < 4; i++) {
        int idx = tid + i*256;
        int arr = idx >> 9;
        int rem = idx & 511;
        int row = rem >> 2;
        int seg = rem & 3;
        uint32_t dst = sbase + arr*ARR_BYTES + row*(PADE*2) + seg*16;
        const __half* src;
        if (arr == 0) { int r = m0 + row; if (r >= M) r = M - 1;
                        src = A + (size_t)r*lda + k0 + seg*8; }
        else          { src = W + (size_t)(n0 + row)*lda + k0 + seg*8; }
        cp16(dst, src);
    }
}

__global__ __launch_bounds__(256, 2)
void gemm_mma(const __half* __restrict__ A,
              const __half* __restrict__ W,
              float* __restrict__ C, int M, int N, int Kc, int lda,
              int mode,
              const float* __restrict__ su, const float* __restrict__ sv,
              __half* __restrict__ hout) {
    extern __shared__ char smem[];
    const uint32_t sb = smem_u32(smem);
    const int tid = threadIdx.x;
    const int lane = tid & 31, wid = tid >> 5;
    const int wm = (wid & 1) * 64;
    const int wn = (wid >> 1) * 32;
    const int m0 = blockIdx.y * BM, n0 = blockIdx.x * BN;
    const int koff = blockIdx.z * Kc;
    C += (size_t)blockIdx.z * M * N;

    float acc[4][4][4] = {};

    const int ntiles = Kc / BK;
    load_stage(sb,                 A, W, m0, n0, koff,        M, lda, tid);
    CP_COMMIT();
    load_stage(sb + STAGE_BYTES,   A, W, m0, n0, koff + BK,   M, lda, tid);
    CP_COMMIT();
    load_stage(sb + 2*STAGE_BYTES, A, W, m0, n0, koff + 2*BK, M, lda, tid);
    CP_COMMIT();

    const int arow = lane & 15, acolsel = (lane >> 4) * 8;

    for (int t = 0; t < ntiles; t++) {
        CP_WAIT2();
        __syncthreads();
        if (t + 3 < ntiles)
            load_stage(sb + ((t + 3) % NSTAGE) * STAGE_BYTES,
                       A, W, m0, n0, koff + (t + 3) * BK, M, lda, tid);
        CP_COMMIT();

        uint32_t sbase = sb + (t % NSTAGE) * STAGE_BYTES;
        const uint32_t sA = sbase;
        const uint32_t sW = sbase + ARR_BYTES;

        #pragma unroll
        for (int ks = 0; ks < 2; ks++) {
            const int kb = ks * 16;
            uint32_t ar[4][4], bw[2][4];
            #pragma unroll
            for (int mt = 0; mt < 4; mt++) {
                uint32_t off = (wm + mt*16 + arow)*(PADE*2) + (kb + acolsel)*2;
                LDSM4(ar[mt], sA + off);
            }
            #pragma unroll
            for (int nb = 0; nb < 2; nb++) {
                uint32_t off = (wn + nb*16 + arow)*(PADE*2) + (kb + acolsel)*2;
                LDSM4(bw[nb], sW + off);
            }
            #pragma unroll
            for (int mt = 0; mt < 4; mt++)
                #pragma unroll
                for (int nb = 0; nb < 2; nb++) {
                    MMA_F16(acc[mt][2*nb],   ar[mt], bw[nb][0], bw[nb][2]);
                    MMA_F16(acc[mt][2*nb+1], ar[mt], bw[nb][1], bw[nb][3]);
                }
        }
        __syncthreads();
    }

    if (mode == 0) {
        #pragma unroll
        for (int mt = 0; mt < 4; mt++) {
            int rbase = m0 + wm + mt*16 + (lane >> 2);
            #pragma unroll
            for (int half = 0; half < 2; half++) {
                int r = rbase + half*8;
                if (r < M) {
                    float* crow = C + (size_t)r*N + n0 + wn + (lane & 3)*2;
                    #pragma unroll
                    for (int nt = 0; nt < 4; nt++) {
                        float2 v = make_float2(acc[mt][nt][half*2],
                                               acc[mt][nt][half*2 + 1]);
                        *reinterpret_cast<float2*>(crow + nt*8) = v;
                    }
                }
            }
        }
    } else if (mode == 1) {
        const int NO = N >> 1;
        #pragma unroll
        for (int mt = 0; mt < 4; mt++) {
            int rbase = m0 + wm + mt*16 + (lane >> 2);
            #pragma unroll
            for (int half = 0; half < 2; half++) {
                int r = rbase + half*8;
                if (r < M) {
                    #pragma unroll
                    for (int nt = 0; nt < 4; nt++) {
                        int cbase = n0 + wn + (lane & 3)*2 + nt*8;
                        int j = cbase >> 1;
                        float u = acc[mt][nt][half*2]     * su[j];
                        float g = acc[mt][nt][half*2 + 1] * sv[j] * SQRTE;
                        float val = u * g / (1.0f + __expf(-g));
                        hout[(size_t)r*NO + j] = __float2half(val);
                    }
                }
            }
        }
    } else {
        #pragma unroll
        for (int mt = 0; mt < 4; mt++) {
            int rbase = m0 + wm + mt*16 + (lane >> 2);
            #pragma unroll
            for (int half = 0; half < 2; half++) {
                int r = rbase + half*8;
                if (r < M) {
                    __half* hrow = hout + (size_t)r*N + n0 + wn + (lane & 3)*2;
                    #pragma unroll
                    for (int nt = 0; nt < 4; nt++) {
                        __half2 v = __half2(__float2half(acc[mt][nt][half*2]),
                                            __float2half(acc[mt][nt][half*2+1]));
                        *reinterpret_cast<__half2*>(hrow + nt*8) = v;
                    }
                }
            }
        }
    }
}

// ======================= tensor-core attention (2-way q-tile split) =========
#define QSTR 72
#define PSTR 216
#define AS_KS (208*QSTR)
#define AS_VT (AS_KS + 208*QSTR)
#define AS_P  (AS_VT + 64*PSTR)
#define AS_HALVES (AS_P + 16*PSTR)
#define ATTN_FLOATS (16 + 64 + 2048)
#define ATTN_BYTES (AS_HALVES*2 + ATTN_FLOATS*4)   // 102,976

__global__ __launch_bounds__(256, 2)
void attn_mma(const __half* __restrict__ qkv,
              const float* __restrict__ s_qk,
              __half* __restrict__ ah) {
    extern __shared__ __half smh[];
    __half* Qs = smh;
    __half* Ks = smh + AS_KS;
    __half* VT = smh + AS_VT;
    __half* P  = smh + AS_P;
    float* fb   = (float*)(smh + AS_HALVES);
    float* rsum = fb;
    float* ss   = fb + 16;
    float* parts= fb + 80;

    const int half_id = blockIdx.x & 1;        // 0: rt 0..6, 1: rt 7..12
    const int bh = blockIdx.x >> 1;
    const int h = bh % H_, b = bh / H_;
    const int rt0 = half_id ? 7 : 0;
    const int rt1 = half_id ? 13 : 7;
    const int tid = threadIdx.x, wid = tid >> 5, lane = tid & 31;
    const __half* base = qkv + (size_t)(b*N_)*(3*E_) + h*HD_;

    if (tid < 64) ss[tid] = s_qk[h*HD_ + tid] * SQRTE;
    __syncthreads();

    // normalize q,k -> fp16 smem; transpose v -> VT
    for (int row = wid; row < N_; row += 8) {
        const __half2* qr = reinterpret_cast<const __half2*>(base + (size_t)row*(3*E_));
        const __half2* kr = reinterpret_cast<const __half2*>(base + (size_t)row*(3*E_) + E_);
        const __half2* vr = reinterpret_cast<const __half2*>(base + (size_t)row*(3*E_) + 2*E_);
        float2 qv = __half22float2(qr[lane]);
        float2 kv = __half22float2(kr[lane]);
        float2 vv = __half22float2(vr[lane]);
        float sq = qv.x*qv.x + qv.y*qv.y;
        float sk = kv.x*kv.x + kv.y*kv.y;
        #pragma unroll
        for (int o = 16; o > 0; o >>= 1) {
            sq += __shfl_xor_sync(~0u, sq, o);
            sk += __shfl_xor_sync(~0u, sk, o);
        }
        float iq = 1.f / fmaxf(sqrtf(sq), 1e-6f);
        float ik = 1.f / fmaxf(sqrtf(sk), 1e-6f);
        float s0 = ss[2*lane], s1 = ss[2*lane + 1];
        reinterpret_cast<__half2*>(Qs + row*QSTR)[lane] =
            __half2(__float2half(qv.x*iq*s0), __float2half(qv.y*iq*s1));
        reinterpret_cast<__half2*>(Ks + row*QSTR)[lane] =
            __half2(__float2half(kv.x*ik*s0), __float2half(kv.y*ik*s1));
        VT[(2*lane)*PSTR + row]     = __float2half(vv.x);
        VT[(2*lane + 1)*PSTR + row] = __float2half(vv.y);
    }
    for (int i = tid; i < 64*11; i += 256) {
        int d = i / 11, m = 197 + i % 11;
        VT[d*PSTR + m] = __float2half(0.f);
    }
    __syncthreads();

    const uint32_t qsa = smem_u32(Qs), ksa = smem_u32(Ks);
    const uint32_t vta = smem_u32(VT), pa = smem_u32(P);
    const int arow = lane & 15, acolsel = (lane >> 4) * 8;
    const __half hz = __float2half(0.f);

    for (int rt = rt0; rt < rt1; rt++) {
        const int q0 = rt * 16;
        for (int nt = wid; nt < 13; nt += 8) {
            float acc[2][4] = {};
            #pragma unroll
            for (int kt = 0; kt < 4; kt++) {
                const int kb = kt * 16;
                uint32_t ar[4], bw[4];
                LDSM4(ar, qsa + (q0 + arow)*(QSTR*2) + (kb + acolsel)*2);
                LDSM4(bw, ksa + (nt*16 + arow)*(QSTR*2) + (kb + acolsel)*2);
                MMA_F16(acc[0], ar, bw[0], bw[2]);
                MMA_F16(acc[1], ar, bw[1], bw[3]);
            }
            int r = lane >> 2;
            #pragma unroll
            for (int f = 0; f < 2; f++) {
                int c0 = nt*16 + (lane & 3)*2 + f*8;
                P[r*PSTR + c0]       = (c0     < N_) ? __float2half(__expf(acc[f][0]*8.f - 8.f)) : hz;
                P[r*PSTR + c0 + 1]   = (c0 + 1 < N_) ? __float2half(__expf(acc[f][1]*8.f - 8.f)) : hz;
                P[(r+8)*PSTR + c0]   = (c0     < N_) ? __float2half(__expf(acc[f][2]*8.f - 8.f)) : hz;
                P[(r+8)*PSTR + c0+1] = (c0 + 1 < N_) ? __float2half(__expf(acc[f][3]*8.f - 8.f)) : hz;
            }
        }
        __syncthreads();
        #pragma unroll
        for (int pass = 0; pass < 2; pass++) {
            int r = wid + pass*8;
            float s = 0.f;
            for (int m = lane; m < 208; m += 32) s += __half2float(P[r*PSTR + m]);
            #pragma unroll
            for (int o = 16; o > 0; o >>= 1) s += __shfl_xor_sync(~0u, s, o);
            if (lane == 0) rsum[r] = 1.f / s;
        }
        {
            const int dt = wid >> 1;
            const int kt0 = (wid & 1) ? 7 : 0;
            const int kt1 = (wid & 1) ? 13 : 7;
            float acc[2][4] = {};
            for (int kt = kt0; kt < kt1; kt++) {
                const int kb = kt * 16;
                uint32_t ar[4], bw[4];
                LDSM4(ar, pa  + arow*(PSTR*2) + (kb + acolsel)*2);
                LDSM4(bw, vta + (dt*16 + arow)*(PSTR*2) + (kb + acolsel)*2);
                MMA_F16(acc[0], ar, bw[0], bw[2]);
                MMA_F16(acc[1], ar, bw[1], bw[3]);
            }
            float* pw = parts + wid*256 + lane*8;
            #pragma unroll
            for (int f = 0; f < 2; f++)
                #pragma unroll
                for (int j = 0; j < 4; j++) pw[f*4 + j] = acc[f][j];
        }
        __syncthreads();
        if (wid < 4) {
            const float* p0 = parts + (2*wid)*256 + lane*8;
            const float* p1 = parts + (2*wid + 1)*256 + lane*8;
            float o8[8];
            #pragma unroll
            for (int i = 0; i < 8; i++) o8[i] = p0[i] + p1[i];
            int r = lane >> 2;
            float i0 = rsum[r], i1 = rsum[r + 8];
            int c0 = wid*16 + (lane & 3)*2;
            int qa = q0 + r, qb2 = q0 + r + 8;
            if (qa < N_) {
                __half2* orow = reinterpret_cast<__half2*>(
                    ah + ((size_t)(b*N_) + qa)*E_ + h*HD_ + c0);
                orow[0] = __half2(__float2half(o8[0]*i0), __float2half(o8[1]*i0));
                orow[4] = __half2(__float2half(o8[4]*i0), __float2half(o8[5]*i0));
            }
            if (qb2 < N_) {
                __half2* orow = reinterpret_cast<__half2*>(
                    ah + ((size_t)(b*N_) + qb2)*E_ + h*HD_ + c0);
                orow[0] = __half2(__float2half(o8[2]*i1), __float2half(o8[3]*i1));
                orow[4] = __half2(__float2half(o8[6]*i1), __float2half(o8[7]*i1));
            }
        }
        __syncthreads();
    }
}

// ---------------- merged weight fp32 -> fp16 repack (single launch) --------
__global__ void cvt_all(const float4* __restrict__ Wq, const float4* __restrict__ Wk,
                        const float4* __restrict__ Wv, const float4* __restrict__ Wo,
                        const float4* __restrict__ Wup, const float4* __restrict__ Wgate,
                        const float4* __restrict__ Wdown, __half2* __restrict__ dst) {
    int i = blockIdx.x * blockDim.x + threadIdx.x;
    const int NQ4 = NQ_/4, NUP4 = NUP_/4, EE4 = EE_/4, FFE4 = FFE_/4;
    float4 x;
    size_t de;
    if (i < 3*NQ4) {
        int f = i / NQ4, rem = i - f*NQ4;
        int l = rem / EE4, j = rem - l*EE4;
        x = (f == 0 ? Wq : (f == 1 ? Wk : Wv))[rem];
        de = (size_t)l*3*EE_ + (size_t)f*EE_ + (size_t)j*4;
    } else if (i < 4*NQ4) {
        int rem = i - 3*NQ4;
        x = Wo[rem];
        de = (size_t)OFF_O + (size_t)rem*4;
    } else if (i < 4*NQ4 + NUP4) {
        int rem = i - 4*NQ4;
        int l = rem / FFE4, j = rem - l*FFE4;
        int r = (j*4) / E_, c = (j*4) % E_;
        x = Wup[rem];
        de = (size_t)OFF_UG + (size_t)l*2*FFE_ + (size_t)(2*r)*E_ + c;
    } else if (i < 4*NQ4 + 2*NUP4) {
        int rem = i - 4*NQ4 - NUP4;
        int l = rem / FFE4, j = rem - l*FFE4;
        int r = (j*4) / E_, c = (j*4) % E_;
        x = Wgate[rem];
        de = (size_t)OFF_UG + (size_t)l*2*FFE_ + (size_t)(2*r + 1)*E_ + c;
    } else if (i < 4*NQ4 + 3*NUP4) {
        int rem = i - 4*NQ4 - 2*NUP4;
        x = Wdown[rem];
        de = (size_t)OFF_DOWN + (size_t)rem*4;
    } else return;
    size_t d2 = de >> 1;
    dst[d2]     = __half2(__float2half(x.x), __float2half(x.y));
    dst[d2 + 1] = __half2(__float2half(x.z), __float2half(x.w));
}

// ---------------- patch embed + CLS row (fp32 h + fp16 act) -----------------
__global__ void patch_embed(const float* __restrict__ x,
                            const float* __restrict__ pw,
                            const float* __restrict__ pb,
                            const float* __restrict__ cls,
                            const float* __restrict__ pos,
                            float* __restrict__ h,
                            __half* __restrict__ ah) {
    int bp = blockIdx.x;
    int b = bp / N_, pr = bp % N_;
    if (pr == 0) {
        for (int e = threadIdx.x; e < E_; e += blockDim.x) {
            float val = cls[e] + pos[e];
            size_t oi = (size_t)(b*N_)*E_ + e;
            h[oi] = val;
            ah[oi] = __float2half(val);
        }
        return;
    }
    int pidx = pr - 1;
    int gi = pidx / 14, gj = pidx % 14;
    __shared__ float patch[768];
    for (int i = threadIdx.x; i < 768; i += blockDim.x) {
        int c  = i >> 8;
        int r  = i & 255;
        int ii = r >> 4, jj = r & 15;
        patch[i] = x[((b*3 + c)*224 + gi*16 + ii)*224 + gj*16 + jj];
    }
    __syncthreads();
    for (int e = threadIdx.x; e < E_; e += blockDim.x) {
        const float* w = pw + e*768;
        float acc = 0.f;
        #pragma unroll 8
        for (int i = 0; i < 768; i++) acc = fmaf(patch[i], w[i], acc);
        float val = acc + pb[e] + pos[(1 + pidx)*E_ + e];
        size_t oi = (size_t)(b*N_ + pr)*E_ + e;
        h[oi] = val;
        ah[oi] = __float2half(val);
    }
}

// ---------------- residual + double cosine-norm (multi-part d, fp16 out) ----
__global__ __launch_bounds__(256)
void res_cn(float* __restrict__ h, const float* __restrict__ d, int nparts,
            const float* __restrict__ alpha,
            __half* __restrict__ ah) {
    int row = blockIdx.x;
    int tid = threadIdx.x;
    const float* dr = d + (size_t)row*E_;
    float* hr = h + (size_t)row*E_;
    __shared__ float red[256];
    float dv[3], hv[3];
    float ss = 0.f;
    #pragma unroll
    for (int t = 0; t < 3; t++) {
        int e = tid + t*256;
        float acc = dr[e];
        for (int p = 1; p < nparts; p++) acc += dr[(size_t)p*PLANE_ + e];
        dv[t] = acc; hv[t] = hr[e];
        ss += dv[t]*dv[t];
    }
    red[tid] = ss; __syncthreads();
    for (int s = 128; s > 0; s >>= 1) {
        if (tid < s) red[tid] += red[tid + s];
        __syncthreads();
    }
    float inv1 = 1.0f / fmaxf(sqrtf(red[0]), 1e-6f);
    __syncthreads();
    float y[3]; float ss2 = 0.f;
    #pragma unroll
    for (int t = 0; t < 3; t++) {
        int e = tid + t*256;
        float a = alpha[e] * (0.05f * SQRTE);
        y[t] = hv[t] + a*(dv[t]*inv1 - hv[t]);
        ss2 += y[t]*y[t];
    }
    red[tid] = ss2; __syncthreads();
    for (int s = 128; s > 0; s >>= 1) {
        if (tid < s) red[tid] += red[tid + s];
        __syncthreads();
    }
    float inv2 = 1.0f / fmaxf(sqrtf(red[0]), 1e-6f);
    #pragma unroll
    for (int t = 0; t < 3; t++) {
        int e = tid + t*256;
        float val = y[t]*inv2;
        hr[e] = val;
        ah[(size_t)row*E_ + e] = __float2half(val);
    }
}

// ---------------- LayerNorm tap -> output (drop CLS token) ------------------
__global__ __launch_bounds__(256)
void ln_out(const float* __restrict__ h, const float* __restrict__ w,
            const float* __restrict__ b, float* __restrict__ o) {
    int br = blockIdx.x;
    int bb = br / NP_, n = br % NP_ + 1;
    const float* hr = h + (size_t)(bb*N_ + n)*E_;
    float* orow = o + (size_t)br*E_;
    __shared__ float red[256];
    int tid = threadIdx.x;
    float vv[3];
    float s = 0.f;
    #pragma unroll
    for (int t = 0; t < 3; t++) { vv[t] = hr[tid + t*256]; s += vv[t]; }
    red[tid] = s; __syncthreads();
    for (int st = 128; st > 0; st >>= 1) {
        if (tid < st) red[tid] += red[tid + st];
        __syncthreads();
    }
    float mean = red[0] * (1.0f/E_);
    __syncthreads();
    float s2 = 0.f;
    #pragma unroll
    for (int t = 0; t < 3; t++) { float dd = vv[t] - mean; s2 += dd*dd; }
    red[tid] = s2; __syncthreads();
    for (int st = 128; st > 0; st >>= 1) {
        if (tid < st) red[tid] += red[tid + st];
        __syncthreads();
    }
    float inv = rsqrtf(red[0]*(1.0f/E_) + 1e-6f);
    #pragma unroll
    for (int t = 0; t < 3; t++) {
        int e = tid + t*256;
        orow[e] = (vv[t] - mean)*inv*w[e] + b[e];
    }
}

// ======================= driver ==============================================
extern "C" void kernel_launch(void* const* d_in, const int* in_sizes, int n_in,
                              void* d_out, int out_size) {
    (void)in_sizes; (void)n_in; (void)out_size;
    const float* x       = (const float*)d_in[0];
    const float* patch_w = (const float*)d_in[1];
    const float* patch_b = (const float*)d_in[2];
    const float* cls     = (const float*)d_in[3];
    const float* pos     = (const float*)d_in[4];
    const float* Wq      = (const float*)d_in[5];
    const float* Wk      = (const float*)d_in[6];
    const float* Wv      = (const float*)d_in[7];
    const float* Wo      = (const float*)d_in[8];
    const float* s_qk    = (const float*)d_in[9];
    const float* Wup     = (const float*)d_in[10];
    const float* Wgate   = (const float*)d_in[11];
    const float* Wdown   = (const float*)d_in[12];
    const float* s_u     = (const float*)d_in[13];
    const float* s_v     = (const float*)d_in[14];
    const float* aA      = (const float*)d_in[15];
    const float* aM      = (const float*)d_in[16];
    const float* fcw     = (const float*)d_in[17];
    const float* fcb     = (const float*)d_in[18];
    float* out = (float*)d_out;

    float *h, *t;
    __half *qkvh, *ah, *a2, *wh;
    cudaGetSymbolAddress((void**)&h,    g_h);
    cudaGetSymbolAddress((void**)&t,    g_t);
    cudaGetSymbolAddress((void**)&qkvh, g_qkvh);
    cudaGetSymbolAddress((void**)&ah,   g_act);
    cudaGetSymbolAddress((void**)&a2,   g_act2);
    cudaGetSymbolAddress((void**)&wh,   g_w);

    cudaFuncSetAttribute(gemm_mma, cudaFuncAttributeMaxDynamicSharedMemorySize, GSMEM);
    cudaFuncSetAttribute(attn_mma, cudaFuncAttributeMaxDynamicSharedMemorySize, ATTN_BYTES);

    cvt_all<<<(WTOT_/4 + 255)/256, 256>>>(
        (const float4*)Wq, (const float4*)Wk, (const float4*)Wv,
        (const float4*)Wo, (const float4*)Wup, (const float4*)Wgate,
        (const float4*)Wdown, (__half2*)wh);

    patch_embed<<<B_*N_, 256>>>(x, patch_w, patch_b, cls, pos, h, ah);

    dim3 gQKV(3*E_/BN, (ROWS_ + BM - 1)/BM, 1);   // (18, 25, 1)
    dim3 gO  (E_/BN,   (ROWS_ + BM - 1)/BM, 2);   // (6, 25, 2)  split-K x2
    dim3 gUG (2*FF_/BN,(ROWS_ + BM - 1)/BM, 1);   // (48, 25, 1)
    dim3 gDN (E_/BN,   (ROWS_ + BM - 1)/BM, 4);   // (6, 25, 4)  split-K x4

    for (int l = 0; l < L_; l++) {
        const size_t oqkv = (size_t)l*3*EE_;
        const size_t oo   = (size_t)l*EE_;
        const size_t oug  = (size_t)l*2*FFE_;
        const size_t od   = (size_t)l*FFE_;
        gemm_mma<<<gQKV, 256, GSMEM>>>(ah, wh+OFF_QKV+oqkv, nullptr, ROWS_, 3*E_,
                                       768, 768, 2, nullptr, nullptr, qkvh);
        attn_mma<<<B_*H_*2, 256, ATTN_BYTES>>>(qkvh, s_qk + (size_t)l*H_*HD_, ah);
        gemm_mma<<<gO, 256, GSMEM>>>(ah, wh+OFF_O+oo, t, ROWS_, E_,
                                     384, 768, 0, nullptr, nullptr, nullptr);
        res_cn<<<ROWS_, 256>>>(h, t, 2, aA + (size_t)l*E_, ah);
        gemm_mma<<<gUG, 256, GSMEM>>>(ah, wh+OFF_UG+oug, nullptr, ROWS_, 2*FF_,
                                      768, 768, 1, s_u + (size_t)l*FF_,
                                      s_v + (size_t)l*FF_, a2);
        gemm_mma<<<gDN, 256, GSMEM>>>(a2, wh+OFF_DOWN+od, t, ROWS_, E_,
                                      768, 3072, 0, nullptr, nullptr, nullptr);
        res_cn<<<ROWS_, 256>>>(h, t, 4, aM + (size_t)l*E_, ah);
        if (l == L_ - 2)
            ln_out<<<B_*NP_, 256>>>(h, fcw, fcb, out);
    }
    ln_out<<<B_*NP_, 256>>>(h, fcw, fcb, out + (size_t)B_*NP_*E_);
}

// round 17
// speedup vs baseline: 1.0213x; 1.0213x over previous
#include <cuda_runtime.h>
#include <cuda_fp16.h>
#include <math.h>
#include <stdint.h>

#define B_   16
#define E_   768
#define H_   12
#define HD_  64
#define N_   197
#define NP_  196
#define L_   12
#define FF_  3072
#define ROWS_ (B_*N_)          // 3152
#define SQRTE 27.712812921102035f
#define EE_   (E_*E_)
#define FFE_  (FF_*E_)
#define PLANE_ (ROWS_*E_)

// packed fp16 weight layout: [QKV(3*NQ)] [O(NQ)] [UG interleaved(2*NUP)] [DOWN(NUP)]
#define NQ_   (L_*EE_)
#define NUP_  (L_*FFE_)
#define OFF_QKV  0
#define OFF_O    (3*NQ_)
#define OFF_UG   (4*NQ_)
#define OFF_DOWN (4*NQ_ + 2*NUP_)
#define WTOT_    (4*NQ_ + 3*NUP_)

// ---------------- scratch (device globals; no allocation allowed) ----------
__device__ float g_h[ROWS_*E_];
__device__ float g_t[4*PLANE_];
__device__ __half g_qkvh[ROWS_*3*E_];
__device__ __half g_act[ROWS_*E_];
__device__ __half g_act2[ROWS_*FF_];
__device__ __half g_w[WTOT_];

// ======================= mma.sync GEMM (unchanged from best) ================
#define BM 128
#define BN 128
#define BK 32
#define PADE 40
#define ARR_BYTES (128*PADE*2)
#define STAGE_BYTES (2*ARR_BYTES)
#define NSTAGE 4
#define GSMEM (NSTAGE*STAGE_BYTES)    // 81920

__device__ __forceinline__ uint32_t smem_u32(const void* p) {
    uint32_t a;
    asm("{ .reg .u64 t; cvta.to.shared.u64 t, %1; cvt.u32.u64 %0, t; }"
        : "=r"(a) : "l"(p));
    return a;
}
__device__ __forceinline__ void cp16(uint32_t dst, const void* src) {
    asm volatile("cp.async.cg.shared.global [%0], [%1], 16;"
                 :: "r"(dst), "l"(src) : "memory");
}
#define CP_COMMIT() asm volatile("cp.async.commit_group;" ::: "memory")
#define CP_WAIT2()  asm volatile("cp.async.wait_group 2;" ::: "memory")

#define LDSM4(r, addr) \
    asm volatile("ldmatrix.sync.aligned.m8n8.x4.shared.b16 {%0,%1,%2,%3}, [%4];" \
        : "=r"((r)[0]), "=r"((r)[1]), "=r"((r)[2]), "=r"((r)[3]) : "r"(addr))
#define MMA_F16(d, a, b0, b1) \
    asm volatile("mma.sync.aligned.m16n8k16.row.col.f32.f16.f16.f32 " \
        "{%0,%1,%2,%3}, {%4,%5,%6,%7}, {%8,%9}, {%0,%1,%2,%3};" \
        : "+f"((d)[0]), "+f"((d)[1]), "+f"((d)[2]), "+f"((d)[3]) \
        : "r"((a)[0]), "r"((a)[1]), "r"((a)[2]), "r"((a)[3]), \
          "r"(b0), "r"(b1))

__device__ __forceinline__ void load_stage(
        uint32_t sbase,
        const __half* __restrict__ A, const __half* __restrict__ W,
        int m0, int n0, int k0, int M, int lda, int tid) {
    #pragma unroll
    for (int i = 0; i < 4; i++) {
        int idx = tid + i*256;
        int arr = idx >> 9;
        int rem = idx & 511;
        int row = rem >> 2;
        int seg = rem & 3;
        uint32_t dst = sbase + arr*ARR_BYTES + row*(PADE*2) + seg*16;
        const __half* src;
        if (arr == 0) { int r = m0 + row; if (r >= M) r = M - 1;
                        src = A + (size_t)r*lda + k0 + seg*8; }
        else          { src = W + (size_t)(n0 + row)*lda + k0 + seg*8; }
        cp16(dst, src);
    }
}

__global__ __launch_bounds__(256, 2)
void gemm_mma(const __half* __restrict__ A,
              const __half* __restrict__ W,
              float* __restrict__ C, int M, int N, int Kc, int lda,
              int mode,
              const float* __restrict__ su, const float* __restrict__ sv,
              __half* __restrict__ hout) {
    extern __shared__ char smem[];
    const uint32_t sb = smem_u32(smem);
    const int tid = threadIdx.x;
    const int lane = tid & 31, wid = tid >> 5;
    const int wm = (wid & 1) * 64;
    const int wn = (wid >> 1) * 32;
    const int m0 = blockIdx.y * BM, n0 = blockIdx.x * BN;
    const int koff = blockIdx.z * Kc;
    C += (size_t)blockIdx.z * M * N;

    float acc[4][4][4] = {};

    const int ntiles = Kc / BK;
    load_stage(sb,                 A, W, m0, n0, koff,        M, lda, tid);
    CP_COMMIT();
    load_stage(sb + STAGE_BYTES,   A, W, m0, n0, koff + BK,   M, lda, tid);
    CP_COMMIT();
    load_stage(sb + 2*STAGE_BYTES, A, W, m0, n0, koff + 2*BK, M, lda, tid);
    CP_COMMIT();

    const int arow = lane & 15, acolsel = (lane >> 4) * 8;

    for (int t = 0; t < ntiles; t++) {
        CP_WAIT2();
        __syncthreads();
        if (t + 3 < ntiles)
            load_stage(sb + ((t + 3) % NSTAGE) * STAGE_BYTES,
                       A, W, m0, n0, koff + (t + 3) * BK, M, lda, tid);
        CP_COMMIT();

        uint32_t sbase = sb + (t % NSTAGE) * STAGE_BYTES;
        const uint32_t sA = sbase;
        const uint32_t sW = sbase + ARR_BYTES;

        #pragma unroll
        for (int ks = 0; ks < 2; ks++) {
            const int kb = ks * 16;
            uint32_t ar[4][4], bw[2][4];
            #pragma unroll
            for (int mt = 0; mt < 4; mt++) {
                uint32_t off = (wm + mt*16 + arow)*(PADE*2) + (kb + acolsel)*2;
                LDSM4(ar[mt], sA + off);
            }
            #pragma unroll
            for (int nb = 0; nb < 2; nb++) {
                uint32_t off = (wn + nb*16 + arow)*(PADE*2) + (kb + acolsel)*2;
                LDSM4(bw[nb], sW + off);
            }
            #pragma unroll
            for (int mt = 0; mt < 4; mt++)
                #pragma unroll
                for (int nb = 0; nb < 2; nb++) {
                    MMA_F16(acc[mt][2*nb],   ar[mt], bw[nb][0], bw[nb][2]);
                    MMA_F16(acc[mt][2*nb+1], ar[mt], bw[nb][1], bw[nb][3]);
                }
        }
        __syncthreads();
    }

    if (mode == 0) {
        #pragma unroll
        for (int mt = 0; mt < 4; mt++) {
            int rbase = m0 + wm + mt*16 + (lane >> 2);
            #pragma unroll
            for (int half = 0; half < 2; half++) {
                int r = rbase + half*8;
                if (r < M) {
                    float* crow = C + (size_t)r*N + n0 + wn + (lane & 3)*2;
                    #pragma unroll
                    for (int nt = 0; nt < 4; nt++) {
                        float2 v = make_float2(acc[mt][nt][half*2],
                                               acc[mt][nt][half*2 + 1]);
                        *reinterpret_cast<float2*>(crow + nt*8) = v;
                    }
                }
            }
        }
    } else if (mode == 1) {
        const int NO = N >> 1;
        #pragma unroll
        for (int mt = 0; mt < 4; mt++) {
            int rbase = m0 + wm + mt*16 + (lane >> 2);
            #pragma unroll
            for (int half = 0; half < 2; half++) {
                int r = rbase + half*8;
                if (r < M) {
                    #pragma unroll
                    for (int nt = 0; nt < 4; nt++) {
                        int cbase = n0 + wn + (lane & 3)*2 + nt*8;
                        int j = cbase >> 1;
                        float u = acc[mt][nt][half*2]     * su[j];
                        float g = acc[mt][nt][half*2 + 1] * sv[j] * SQRTE;
                        float val = u * g / (1.0f + __expf(-g));
                        hout[(size_t)r*NO + j] = __float2half(val);
                    }
                }
            }
        }
    } else {
        #pragma unroll
        for (int mt = 0; mt < 4; mt++) {
            int rbase = m0 + wm + mt*16 + (lane >> 2);
            #pragma unroll
            for (int half = 0; half < 2; half++) {
                int r = rbase + half*8;
                if (r < M) {
                    __half* hrow = hout + (size_t)r*N + n0 + wn + (lane & 3)*2;
                    #pragma unroll
                    for (int nt = 0; nt < 4; nt++) {
                        __half2 v = __half2(__float2half(acc[mt][nt][half*2]),
                                            __float2half(acc[mt][nt][half*2+1]));
                        *reinterpret_cast<__half2*>(hrow + nt*8) = v;
                    }
                }
            }
        }
    }
}

// ======================= tensor-core attention (R15 best form) ==============
#define QSTR 72
#define PSTR 216
#define AS_KS (208*QSTR)
#define AS_VT (AS_KS + 208*QSTR)
#define AS_P  (AS_VT + 64*PSTR)
#define AS_HALVES (AS_P + 16*PSTR)
#define ATTN_FLOATS (16 + 64 + 2048)
#define ATTN_BYTES (AS_HALVES*2 + ATTN_FLOATS*4)   // 102,976

__global__ __launch_bounds__(256, 2)
void attn_mma(const __half* __restrict__ qkv,
              const float* __restrict__ s_qk,
              __half* __restrict__ ah) {
    extern __shared__ __half smh[];
    __half* Qs = smh;
    __half* Ks = smh + AS_KS;
    __half* VT = smh + AS_VT;
    __half* P  = smh + AS_P;
    float* fb   = (float*)(smh + AS_HALVES);
    float* rsum = fb;
    float* ss   = fb + 16;
    float* parts= fb + 80;

    const int bh = blockIdx.x;
    const int h = bh % H_, b = bh / H_;
    const int tid = threadIdx.x, wid = tid >> 5, lane = tid & 31;
    const __half* base = qkv + (size_t)(b*N_)*(3*E_) + h*HD_;

    if (tid < 64) ss[tid] = s_qk[h*HD_ + tid] * SQRTE;
    __syncthreads();

    for (int row = wid; row < N_; row += 8) {
        const __half2* qr = reinterpret_cast<const __half2*>(base + (size_t)row*(3*E_));
        const __half2* kr = reinterpret_cast<const __half2*>(base + (size_t)row*(3*E_) + E_);
        const __half2* vr = reinterpret_cast<const __half2*>(base + (size_t)row*(3*E_) + 2*E_);
        float2 qv = __half22float2(qr[lane]);
        float2 kv = __half22float2(kr[lane]);
        float2 vv = __half22float2(vr[lane]);
        float sq = qv.x*qv.x + qv.y*qv.y;
        float sk = kv.x*kv.x + kv.y*kv.y;
        #pragma unroll
        for (int o = 16; o > 0; o >>= 1) {
            sq += __shfl_xor_sync(~0u, sq, o);
            sk += __shfl_xor_sync(~0u, sk, o);
        }
        float iq = 1.f / fmaxf(sqrtf(sq), 1e-6f);
        float ik = 1.f / fmaxf(sqrtf(sk), 1e-6f);
        float s0 = ss[2*lane], s1 = ss[2*lane + 1];
        reinterpret_cast<__half2*>(Qs + row*QSTR)[lane] =
            __half2(__float2half(qv.x*iq*s0), __float2half(qv.y*iq*s1));
        reinterpret_cast<__half2*>(Ks + row*QSTR)[lane] =
            __half2(__float2half(kv.x*ik*s0), __float2half(kv.y*ik*s1));
        VT[(2*lane)*PSTR + row]     = __float2half(vv.x);
        VT[(2*lane + 1)*PSTR + row] = __float2half(vv.y);
    }
    for (int i = tid; i < 64*11; i += 256) {
        int d = i / 11, m = 197 + i % 11;
        VT[d*PSTR + m] = __float2half(0.f);
    }
    __syncthreads();

    const uint32_t qsa = smem_u32(Qs), ksa = smem_u32(Ks);
    const uint32_t vta = smem_u32(VT), pa = smem_u32(P);
    const int arow = lane & 15, acolsel = (lane >> 4) * 8;
    const __half hz = __float2half(0.f);

    for (int rt = 0; rt < 13; rt++) {
        const int q0 = rt * 16;
        for (int nt = wid; nt < 13; nt += 8) {
            float acc[2][4] = {};
            #pragma unroll
            for (int kt = 0; kt < 4; kt++) {
                const int kb = kt * 16;
                uint32_t ar[4], bw[4];
                LDSM4(ar, qsa + (q0 + arow)*(QSTR*2) + (kb + acolsel)*2);
                LDSM4(bw, ksa + (nt*16 + arow)*(QSTR*2) + (kb + acolsel)*2);
                MMA_F16(acc[0], ar, bw[0], bw[2]);
                MMA_F16(acc[1], ar, bw[1], bw[3]);
            }
            int r = lane >> 2;
            #pragma unroll
            for (int f = 0; f < 2; f++) {
                int c0 = nt*16 + (lane & 3)*2 + f*8;
                P[r*PSTR + c0]       = (c0     < N_) ? __float2half(__expf(acc[f][0]*8.f - 8.f)) : hz;
                P[r*PSTR + c0 + 1]   = (c0 + 1 < N_) ? __float2half(__expf(acc[f][1]*8.f - 8.f)) : hz;
                P[(r+8)*PSTR + c0]   = (c0     < N_) ? __float2half(__expf(acc[f][2]*8.f - 8.f)) : hz;
                P[(r+8)*PSTR + c0+1] = (c0 + 1 < N_) ? __float2half(__expf(acc[f][3]*8.f - 8.f)) : hz;
            }
        }
        __syncthreads();
        #pragma unroll
        for (int pass = 0; pass < 2; pass++) {
            int r = wid + pass*8;
            float s = 0.f;
            for (int m = lane; m < 208; m += 32) s += __half2float(P[r*PSTR + m]);
            #pragma unroll
            for (int o = 16; o > 0; o >>= 1) s += __shfl_xor_sync(~0u, s, o);
            if (lane == 0) rsum[r] = 1.f / s;
        }
        {
            const int dt = wid >> 1;
            const int kt0 = (wid & 1) ? 7 : 0;
            const int kt1 = (wid & 1) ? 13 : 7;
            float acc[2][4] = {};
            for (int kt = kt0; kt < kt1; kt++) {
                const int kb = kt * 16;
                uint32_t ar[4], bw[4];
                LDSM4(ar, pa  + arow*(PSTR*2) + (kb + acolsel)*2);
                LDSM4(bw, vta + (dt*16 + arow)*(PSTR*2) + (kb + acolsel)*2);
                MMA_F16(acc[0], ar, bw[0], bw[2]);
                MMA_F16(acc[1], ar, bw[1], bw[3]);
            }
            float* pw = parts + wid*256 + lane*8;
            #pragma unroll
            for (int f = 0; f < 2; f++)
                #pragma unroll
                for (int j = 0; j < 4; j++) pw[f*4 + j] = acc[f][j];
        }
        __syncthreads();
        if (wid < 4) {
            const float* p0 = parts + (2*wid)*256 + lane*8;
            const float* p1 = parts + (2*wid + 1)*256 + lane*8;
            float o8[8];
            #pragma unroll
            for (int i = 0; i < 8; i++) o8[i] = p0[i] + p1[i];
            int r = lane >> 2;
            float i0 = rsum[r], i1 = rsum[r + 8];
            int c0 = wid*16 + (lane & 3)*2;
            int qa = q0 + r, qb2 = q0 + r + 8;
            if (qa < N_) {
                __half2* orow = reinterpret_cast<__half2*>(
                    ah + ((size_t)(b*N_) + qa)*E_ + h*HD_ + c0);
                orow[0] = __half2(__float2half(o8[0]*i0), __float2half(o8[1]*i0));
                orow[4] = __half2(__float2half(o8[4]*i0), __float2half(o8[5]*i0));
            }
            if (qb2 < N_) {
                __half2* orow = reinterpret_cast<__half2*>(
                    ah + ((size_t)(b*N_) + qb2)*E_ + h*HD_ + c0);
                orow[0] = __half2(__float2half(o8[2]*i1), __float2half(o8[3]*i1));
                orow[4] = __half2(__float2half(o8[6]*i1), __float2half(o8[7]*i1));
            }
        }
        __syncthreads();
    }
}

// ---------------- merged weight fp32 -> fp16 repack (single launch) --------
__global__ void cvt_all(const float4* __restrict__ Wq, const float4* __restrict__ Wk,
                        const float4* __restrict__ Wv, const float4* __restrict__ Wo,
                        const float4* __restrict__ Wup, const float4* __restrict__ Wgate,
                        const float4* __restrict__ Wdown, __half2* __restrict__ dst) {
    int i = blockIdx.x * blockDim.x + threadIdx.x;
    const int NQ4 = NQ_/4, NUP4 = NUP_/4, EE4 = EE_/4, FFE4 = FFE_/4;
    float4 x;
    size_t de;
    if (i < 3*NQ4) {
        int f = i / NQ4, rem = i - f*NQ4;
        int l = rem / EE4, j = rem - l*EE4;
        x = (f == 0 ? Wq : (f == 1 ? Wk : Wv))[rem];
        de = (size_t)l*3*EE_ + (size_t)f*EE_ + (size_t)j*4;
    } else if (i < 4*NQ4) {
        int rem = i - 3*NQ4;
        x = Wo[rem];
        de = (size_t)OFF_O + (size_t)rem*4;
    } else if (i < 4*NQ4 + NUP4) {
        int rem = i - 4*NQ4;
        int l = rem / FFE4, j = rem - l*FFE4;
        int r = (j*4) / E_, c = (j*4) % E_;
        x = Wup[rem];
        de = (size_t)OFF_UG + (size_t)l*2*FFE_ + (size_t)(2*r)*E_ + c;
    } else if (i < 4*NQ4 + 2*NUP4) {
        int rem = i - 4*NQ4 - NUP4;
        int l = rem / FFE4, j = rem - l*FFE4;
        int r = (j*4) / E_, c = (j*4) % E_;
        x = Wgate[rem];
        de = (size_t)OFF_UG + (size_t)l*2*FFE_ + (size_t)(2*r + 1)*E_ + c;
    } else if (i < 4*NQ4 + 3*NUP4) {
        int rem = i - 4*NQ4 - 2*NUP4;
        x = Wdown[rem];
        de = (size_t)OFF_DOWN + (size_t)rem*4;
    } else return;
    size_t d2 = de >> 1;
    dst[d2]     = __half2(__float2half(x.x), __float2half(x.y));
    dst[d2 + 1] = __half2(__float2half(x.z), __float2half(x.w));
}

// ---------------- patch embed + CLS row (fp32 h + fp16 act) -----------------
__global__ void patch_embed(const float* __restrict__ x,
                            const float* __restrict__ pw,
                            const float* __restrict__ pb,
                            const float* __restrict__ cls,
                            const float* __restrict__ pos,
                            float* __restrict__ h,
                            __half* __restrict__ ah) {
    int bp = blockIdx.x;
    int b = bp / N_, pr = bp % N_;
    if (pr == 0) {
        for (int e = threadIdx.x; e < E_; e += blockDim.x) {
            float val = cls[e] + pos[e];
            size_t oi = (size_t)(b*N_)*E_ + e;
            h[oi] = val;
            ah[oi] = __float2half(val);
        }
        return;
    }
    int pidx = pr - 1;
    int gi = pidx / 14, gj = pidx % 14;
    __shared__ float patch[768];
    for (int i = threadIdx.x; i < 768; i += blockDim.x) {
        int c  = i >> 8;
        int r  = i & 255;
        int ii = r >> 4, jj = r & 15;
        patch[i] = x[((b*3 + c)*224 + gi*16 + ii)*224 + gj*16 + jj];
    }
    __syncthreads();
    for (int e = threadIdx.x; e < E_; e += blockDim.x) {
        const float* w = pw + e*768;
        float acc = 0.f;
        #pragma unroll 8
        for (int i = 0; i < 768; i++) acc = fmaf(patch[i], w[i], acc);
        float val = acc + pb[e] + pos[(1 + pidx)*E_ + e];
        size_t oi = (size_t)(b*N_ + pr)*E_ + e;
        h[oi] = val;
        ah[oi] = __float2half(val);
    }
}

// ---------------- residual + double cosine-norm (multi-part d, fp16 out) ----
__global__ __launch_bounds__(256)
void res_cn(float* __restrict__ h, const float* __restrict__ d, int nparts,
            const float* __restrict__ alpha,
            __half* __restrict__ ah) {
    int row = blockIdx.x;
    int tid = threadIdx.x;
    const float* dr = d + (size_t)row*E_;
    float* hr = h + (size_t)row*E_;
    __shared__ float red[256];
    float dv[3], hv[3];
    float ss = 0.f;
    #pragma unroll
    for (int t = 0; t < 3; t++) {
        int e = tid + t*256;
        float acc = dr[e];
        for (int p = 1; p < nparts; p++) acc += dr[(size_t)p*PLANE_ + e];
        dv[t] = acc; hv[t] = hr[e];
        ss += dv[t]*dv[t];
    }
    red[tid] = ss; __syncthreads();
    for (int s = 128; s > 0; s >>= 1) {
        if (tid < s) red[tid] += red[tid + s];
        __syncthreads();
    }
    float inv1 = 1.0f / fmaxf(sqrtf(red[0]), 1e-6f);
    __syncthreads();
    float y[3]; float ss2 = 0.f;
    #pragma unroll
    for (int t = 0; t < 3; t++) {
        int e = tid + t*256;
        float a = alpha[e] * (0.05f * SQRTE);
        y[t] = hv[t] + a*(dv[t]*inv1 - hv[t]);
        ss2 += y[t]*y[t];
    }
    red[tid] = ss2; __syncthreads();
    for (int s = 128; s > 0; s >>= 1) {
        if (tid < s) red[tid] += red[tid + s];
        __syncthreads();
    }
    float inv2 = 1.0f / fmaxf(sqrtf(red[0]), 1e-6f);
    #pragma unroll
    for (int t = 0; t < 3; t++) {
        int e = tid + t*256;
        float val = y[t]*inv2;
        hr[e] = val;
        ah[(size_t)row*E_ + e] = __float2half(val);
    }
}

// ---------------- LayerNorm tap -> output (drop CLS token) ------------------
__global__ __launch_bounds__(256)
void ln_out(const float* __restrict__ h, const float* __restrict__ w,
            const float* __restrict__ b, float* __restrict__ o) {
    int br = blockIdx.x;
    int bb = br / NP_, n = br % NP_ + 1;
    const float* hr = h + (size_t)(bb*N_ + n)*E_;
    float* orow = o + (size_t)br*E_;
    __shared__ float red[256];
    int tid = threadIdx.x;
    float vv[3];
    float s = 0.f;
    #pragma unroll
    for (int t = 0; t < 3; t++) { vv[t] = hr[tid + t*256]; s += vv[t]; }
    red[tid] = s; __syncthreads();
    for (int st = 128; st > 0; st >>= 1) {
        if (tid < st) red[tid] += red[tid + st];
        __syncthreads();
    }
    float mean = red[0] * (1.0f/E_);
    __syncthreads();
    float s2 = 0.f;
    #pragma unroll
    for (int t = 0; t < 3; t++) { float dd = vv[t] - mean; s2 += dd*dd; }
    red[tid] = s2; __syncthreads();
    for (int st = 128; st > 0; st >>= 1) {
        if (tid < st) red[tid] += red[tid + st];
        __syncthreads();
    }
    float inv = rsqrtf(red[0]*(1.0f/E_) + 1e-6f);
    #pragma unroll
    for (int t = 0; t < 3; t++) {
        int e = tid + t*256;
        orow[e] = (vv[t] - mean)*inv*w[e] + b[e];
    }
}

// ======================= driver ==============================================
extern "C" void kernel_launch(void* const* d_in, const int* in_sizes, int n_in,
                              void* d_out, int out_size) {
    (void)in_sizes; (void)n_in; (void)out_size;
    const float* x       = (const float*)d_in[0];
    const float* patch_w = (const float*)d_in[1];
    const float* patch_b = (const float*)d_in[2];
    const float* cls     = (const float*)d_in[3];
    const float* pos     = (const float*)d_in[4];
    const float* Wq      = (const float*)d_in[5];
    const float* Wk      = (const float*)d_in[6];
    const float* Wv      = (const float*)d_in[7];
    const float* Wo      = (const float*)d_in[8];
    const float* s_qk    = (const float*)d_in[9];
    const float* Wup     = (const float*)d_in[10];
    const float* Wgate   = (const float*)d_in[11];
    const float* Wdown   = (const float*)d_in[12];
    const float* s_u     = (const float*)d_in[13];
    const float* s_v     = (const float*)d_in[14];
    const float* aA      = (const float*)d_in[15];
    const float* aM      = (const float*)d_in[16];
    const float* fcw     = (const float*)d_in[17];
    const float* fcb     = (const float*)d_in[18];
    float* out = (float*)d_out;

    float *h, *t;
    __half *qkvh, *ah, *a2, *wh;
    cudaGetSymbolAddress((void**)&h,    g_h);
    cudaGetSymbolAddress((void**)&t,    g_t);
    cudaGetSymbolAddress((void**)&qkvh, g_qkvh);
    cudaGetSymbolAddress((void**)&ah,   g_act);
    cudaGetSymbolAddress((void**)&a2,   g_act2);
    cudaGetSymbolAddress((void**)&wh,   g_w);

    cudaFuncSetAttribute(gemm_mma, cudaFuncAttributeMaxDynamicSharedMemorySize, GSMEM);
    cudaFuncSetAttribute(attn_mma, cudaFuncAttributeMaxDynamicSharedMemorySize, ATTN_BYTES);

    cvt_all<<<(WTOT_/4 + 255)/256, 256>>>(
        (const float4*)Wq, (const float4*)Wk, (const float4*)Wv,
        (const float4*)Wo, (const float4*)Wup, (const float4*)Wgate,
        (const float4*)Wdown, (__half2*)wh);

    patch_embed<<<B_*N_, 256>>>(x, patch_w, patch_b, cls, pos, h, ah);

    dim3 gQKV(3*E_/BN, (ROWS_ + BM - 1)/BM, 1);   // (18, 25, 1)
    dim3 gO  (E_/BN,   (ROWS_ + BM - 1)/BM, 2);   // (6, 25, 2)  split-K x2
    dim3 gUG (2*FF_/BN,(ROWS_ + BM - 1)/BM, 1);   // (48, 25, 1)
    dim3 gDN (E_/BN,   (ROWS_ + BM - 1)/BM, 2);   // (6, 25, 2)  split-K x2 (1.01 waves)

    for (int l = 0; l < L_; l++) {
        const size_t oqkv = (size_t)l*3*EE_;
        const size_t oo   = (size_t)l*EE_;
        const size_t oug  = (size_t)l*2*FFE_;
        const size_t od   = (size_t)l*FFE_;
        gemm_mma<<<gQKV, 256, GSMEM>>>(ah, wh+OFF_QKV+oqkv, nullptr, ROWS_, 3*E_,
                                       768, 768, 2, nullptr, nullptr, qkvh);
        attn_mma<<<B_*H_, 256, ATTN_BYTES>>>(qkvh, s_qk + (size_t)l*H_*HD_, ah);
        gemm_mma<<<gO, 256, GSMEM>>>(ah, wh+OFF_O+oo, t, ROWS_, E_,
                                     384, 768, 0, nullptr, nullptr, nullptr);
        res_cn<<<ROWS_, 256>>>(h, t, 2, aA + (size_t)l*E_, ah);
        gemm_mma<<<gUG, 256, GSMEM>>>(ah, wh+OFF_UG+oug, nullptr, ROWS_, 2*FF_,
                                      768, 768, 1, s_u + (size_t)l*FF_,
                                      s_v + (size_t)l*FF_, a2);
        gemm_mma<<<gDN, 256, GSMEM>>>(a2, wh+OFF_DOWN+od, t, ROWS_, E_,
                                      1536, 3072, 0, nullptr, nullptr, nullptr);
        res_cn<<<ROWS_, 256>>>(h, t, 2, aM + (size_t)l*E_, ah);
        if (l == L_ - 2)
            ln_out<<<B_*NP_, 256>>>(h, fcw, fcb, out);
    }
    ln_out<<<B_*NP_, 256>>>(h, fcw, fcb, out + (size_t)B_*NP_*E_);
}